// round 5
// baseline (speedup 1.0000x reference)
#include <cuda_runtime.h>
#include <cuda_bf16.h>
#include <cstdint>
#include <math.h>

// Problem constants (fixed by the dataset)
#define NA      50000
#define NP      10000
#define NE      400000
#define IN_DIM  512
#define FEAT    128
#define NH      8
#define OD      32
#define HD      256   // NH*OD

// ---------------- scratch (static device globals; no allocation) -----------
__device__ float g_z[(size_t)NA * HD];        // 51.2 MB
__device__ float g_ssrc[(size_t)NA * NH];
__device__ float g_eval[(size_t)NE * NH];
__device__ float g_vfeat[NH * FEAT];
__device__ int   g_counts[NP];
__device__ int   g_offsets[NP];
__device__ int   g_cursor[NP];
__device__ int   g_edge_sorted[NE];
// pre-split bf16 hi/lo operands
__device__ __nv_bfloat16 g_ahi[(size_t)NA * IN_DIM];   // 51.2 MB
__device__ __nv_bfloat16 g_alo[(size_t)NA * IN_DIM];   // 51.2 MB
__device__ __nv_bfloat16 g_bhi[(size_t)HD * IN_DIM];   // 256 KB
__device__ __nv_bfloat16 g_blo[(size_t)HD * IN_DIM];   // 256 KB

// ---------------- small utility kernels ------------------------------------
__global__ void k_zero_counts() {
    int t = blockIdx.x * blockDim.x + threadIdx.x;
    if (t < NP) g_counts[t] = 0;
}

__global__ void k_vfeat(const float* __restrict__ W_feat,
                        const float* __restrict__ W_attn) {
    int t = blockIdx.x * blockDim.x + threadIdx.x;
    if (t >= NH * FEAT) return;
    int h = t / FEAT, f = t % FEAT;
    float acc = 0.f;
#pragma unroll
    for (int d = 0; d < OD; ++d)
        acc += W_attn[2 * OD + d] * W_feat[(size_t)(h * OD + d) * FEAT + f];
    g_vfeat[t] = acc;
}

// ---------------- fp32 -> bf16 hi/lo split (bandwidth pass) -----------------
__global__ void __launch_bounds__(256) k_split(const float* __restrict__ src,
                                               __nv_bfloat16* __restrict__ hi,
                                               __nv_bfloat16* __restrict__ lo,
                                               int n4) {
    int t = blockIdx.x * blockDim.x + threadIdx.x;
    if (t >= n4) return;
    float4 v = ((const float4*)src)[t];
    __nv_bfloat16 hx = __float2bfloat16_rn(v.x);
    __nv_bfloat16 hy = __float2bfloat16_rn(v.y);
    __nv_bfloat16 hz = __float2bfloat16_rn(v.z);
    __nv_bfloat16 hw = __float2bfloat16_rn(v.w);
    __nv_bfloat162 h0 = __halves2bfloat162(hx, hy);
    __nv_bfloat162 h1 = __halves2bfloat162(hz, hw);
    __nv_bfloat162 l0 = __floats2bfloat162_rn(v.x - __bfloat162float(hx),
                                              v.y - __bfloat162float(hy));
    __nv_bfloat162 l1 = __floats2bfloat162_rn(v.z - __bfloat162float(hz),
                                              v.w - __bfloat162float(hw));
    uint2 hp = make_uint2(*(uint32_t*)&h0, *(uint32_t*)&h1);
    uint2 lp = make_uint2(*(uint32_t*)&l0, *(uint32_t*)&l1);
    ((uint2*)hi)[t] = hp;
    ((uint2*)lo)[t] = lp;
}

// ============ 3-term compensated bf16 GEMM, cp.async pipeline ===============
// C[M,N] = A @ B^T ;  C += Al*Bh + Ah*Bl + Ah*Bh   (A/B pre-split bf16)
// Block 128x128x32, warps 2(m)x4(n), warp tile 64x32, mma m16n8k16.
#define GBM 128
#define GBN 128
#define GBK 32
#define KP  (GBK / 2)          // 16 uint32 (bf16x2 pairs) per row
#define SPAD 4
#define SSTR (KP + SPAD)       // 20 words; 16B-aligned rows, conflict-free frags

#define SIDX(buf, row, kp) ((((buf) * GBM) + (row)) * SSTR + (kp))
#define TILE_WORDS (2 * GBM * SSTR)                 // per hi/lo array (2 bufs)
#define GEMM_SMEM_BYTES (4 * TILE_WORDS * 4)        // 81920 = 80KB

__device__ __forceinline__ void cp16(uint32_t dst, const void* src, int srcsize) {
    asm volatile("cp.async.cg.shared.global [%0], [%1], 16, %2;\n"
                 :: "r"(dst), "l"(src), "r"(srcsize));
}

#define MMA_BF16(D, A0, A1, A2, A3, B0, B1)                                   \
    asm volatile(                                                             \
        "mma.sync.aligned.m16n8k16.row.col.f32.bf16.bf16.f32 "                \
        "{%0,%1,%2,%3}, {%4,%5,%6,%7}, {%8,%9}, {%0,%1,%2,%3};"               \
        : "+f"(D[0]), "+f"(D[1]), "+f"(D[2]), "+f"(D[3])                      \
        : "r"(A0), "r"(A1), "r"(A2), "r"(A3), "r"(B0), "r"(B1))

__global__ void __launch_bounds__(256, 2)
k_gemm_bf16pre(const __nv_bfloat16* __restrict__ Ahg,
               const __nv_bfloat16* __restrict__ Alg,
               const __nv_bfloat16* __restrict__ Bhg,
               const __nv_bfloat16* __restrict__ Blg,
               float* __restrict__ C) {
    const int M = NA, K = IN_DIM;
    extern __shared__ uint32_t sm[];
    uint32_t* Ah = sm;
    uint32_t* Al = sm + TILE_WORDS;
    uint32_t* Bh = sm + 2 * TILE_WORDS;
    uint32_t* Bl = sm + 3 * TILE_WORDS;

    const int bm = blockIdx.y * GBM;
    const int bn = blockIdx.x * GBN;
    const int tid = threadIdx.x;
    const int warp = tid >> 5, lane = tid & 31;
    const int g = lane >> 2, tg = lane & 3;
    const int wm = (warp >> 2) * 64;
    const int wn = (warp & 3) * 32;

    float acc[4][4][4];
#pragma unroll
    for (int mi = 0; mi < 4; ++mi)
#pragma unroll
        for (int nj = 0; nj < 4; ++nj)
#pragma unroll
            for (int r = 0; r < 4; ++r) acc[mi][nj][r] = 0.f;

    // loader mapping: 512 16B-chunks per tile; thread does chunks tid, tid+256
    const int NITER = K / GBK;   // 16

    // ---- issue loads for k-tile `t` into buffer `buf`
    auto issue = [&](int t, int buf) {
        int kb = t * GBK;
#pragma unroll
        for (int it = 0; it < 2; ++it) {
            int chunk = tid + it * 256;
            int row = chunk >> 2;            // 0..127
            int coff = (chunk & 3) * 8;      // bf16 offset within 32-wide k
            int woff = (chunk & 3) * 4;      // word offset (16B aligned)
            int grow = bm + row;
            const __nv_bfloat16* asrc = Ahg + (size_t)grow * K + kb + coff;
            const __nv_bfloat16* asrc2 = Alg + (size_t)grow * K + kb + coff;
            int ok = (grow < M) ? 16 : 0;
            cp16((uint32_t)__cvta_generic_to_shared(&Ah[SIDX(buf, row, woff)]), asrc, ok);
            cp16((uint32_t)__cvta_generic_to_shared(&Al[SIDX(buf, row, woff)]), asrc2, ok);
            int brow = bn + row;
            cp16((uint32_t)__cvta_generic_to_shared(&Bh[SIDX(buf, row, woff)]),
                 Bhg + (size_t)brow * K + kb + coff, 16);
            cp16((uint32_t)__cvta_generic_to_shared(&Bl[SIDX(buf, row, woff)]),
                 Blg + (size_t)brow * K + kb + coff, 16);
        }
        asm volatile("cp.async.commit_group;\n" ::);
    };

    issue(0, 0);

    for (int t = 0; t < NITER; ++t) {
        asm volatile("cp.async.wait_group 0;\n" ::);
        __syncthreads();
        if (t + 1 < NITER) issue(t + 1, (t + 1) & 1);

        const int buf = t & 1;
#pragma unroll
        for (int ks = 0; ks < 2; ++ks) {
            const int kw = ks * 8;   // word base for this k16 step
            uint32_t bhf[4][2], blf[4][2];
#pragma unroll
            for (int nj = 0; nj < 4; ++nj) {
                int row = wn + nj * 8 + g;
                bhf[nj][0] = Bh[SIDX(buf, row, kw + tg)];
                bhf[nj][1] = Bh[SIDX(buf, row, kw + tg + 4)];
                blf[nj][0] = Bl[SIDX(buf, row, kw + tg)];
                blf[nj][1] = Bl[SIDX(buf, row, kw + tg + 4)];
            }
#pragma unroll
            for (int mi = 0; mi < 4; ++mi) {
                int r0 = wm + mi * 16 + g;
                uint32_t ah0 = Ah[SIDX(buf, r0, kw + tg)];
                uint32_t ah1 = Ah[SIDX(buf, r0 + 8, kw + tg)];
                uint32_t ah2 = Ah[SIDX(buf, r0, kw + tg + 4)];
                uint32_t ah3 = Ah[SIDX(buf, r0 + 8, kw + tg + 4)];
                uint32_t al0 = Al[SIDX(buf, r0, kw + tg)];
                uint32_t al1 = Al[SIDX(buf, r0 + 8, kw + tg)];
                uint32_t al2 = Al[SIDX(buf, r0, kw + tg + 4)];
                uint32_t al3 = Al[SIDX(buf, r0 + 8, kw + tg + 4)];
#pragma unroll
                for (int nj = 0; nj < 4; ++nj) {
                    MMA_BF16(acc[mi][nj], al0, al1, al2, al3, bhf[nj][0], bhf[nj][1]);
                    MMA_BF16(acc[mi][nj], ah0, ah1, ah2, ah3, blf[nj][0], blf[nj][1]);
                    MMA_BF16(acc[mi][nj], ah0, ah1, ah2, ah3, bhf[nj][0], bhf[nj][1]);
                }
            }
        }
        __syncthreads();
    }

    // ---- epilogue
#pragma unroll
    for (int mi = 0; mi < 4; ++mi) {
        int row0 = bm + wm + mi * 16 + g;
#pragma unroll
        for (int nj = 0; nj < 4; ++nj) {
            int col = bn + wn + nj * 8 + tg * 2;
            if (row0 < M)
                *(float2*)&C[(size_t)row0 * HD + col] =
                    make_float2(acc[mi][nj][0], acc[mi][nj][1]);
            if (row0 + 8 < M)
                *(float2*)&C[(size_t)(row0 + 8) * HD + col] =
                    make_float2(acc[mi][nj][2], acc[mi][nj][3]);
        }
    }
}

// ---------------- s_src[n,h] = z[n,h,:] . a_src  (warp per node) ------------
__global__ void __launch_bounds__(256) k_ssrc(const float* __restrict__ W_attn) {
    int gw = (blockIdx.x * blockDim.x + threadIdx.x) >> 5;
    int lane = threadIdx.x & 31;
    if (gw >= NA) return;
    const float4* zp = (const float4*)(g_z + (size_t)gw * HD);
    float4 v0 = zp[lane];
    float4 v1 = zp[lane + 32];
    float4 a4 = *(const float4*)(W_attn + (lane & 7) * 4);
    float acc0 = v0.x * a4.x + v0.y * a4.y + v0.z * a4.z + v0.w * a4.w;
    float acc1 = v1.x * a4.x + v1.y * a4.y + v1.z * a4.z + v1.w * a4.w;
#pragma unroll
    for (int off = 1; off < 8; off <<= 1) {
        acc0 += __shfl_xor_sync(0xffffffffu, acc0, off);
        acc1 += __shfl_xor_sync(0xffffffffu, acc1, off);
    }
    if ((lane & 7) == 0) {
        g_ssrc[(size_t)gw * NH + (lane >> 3)] = acc0;
        g_ssrc[(size_t)gw * NH + 4 + (lane >> 3)] = acc1;
    }
}

// ---------------- edge scores ------------------------------------------------
__global__ void __launch_bounds__(256) k_eval(const float* __restrict__ srl,
                                              const int* __restrict__ src) {
    __shared__ float sv[NH][FEAT];
    int tid = threadIdx.x;
#pragma unroll
    for (int i = tid; i < NH * FEAT; i += 256)
        ((float*)sv)[i] = g_vfeat[i];
    __syncthreads();

    int warp = tid >> 5, lane = tid & 31;
    int grp = lane >> 3, sl = lane & 7;
    int e = blockIdx.x * 32 + warp * 4 + grp;
    if (e >= NE) return;

    const float4* row = (const float4*)(srl + (size_t)e * FEAT);
    float acc[NH];
#pragma unroll
    for (int h = 0; h < NH; ++h) acc[h] = 0.f;
#pragma unroll
    for (int i = 0; i < 4; ++i) {
        float4 v = row[i * 8 + sl];
        int fb = (i * 8 + sl) * 4;
#pragma unroll
        for (int h = 0; h < NH; ++h) {
            acc[h] += v.x * sv[h][fb + 0];
            acc[h] += v.y * sv[h][fb + 1];
            acc[h] += v.z * sv[h][fb + 2];
            acc[h] += v.w * sv[h][fb + 3];
        }
    }
    float ev = 0.f;
#pragma unroll
    for (int h = 0; h < NH; ++h) {
        float v = acc[h];
        v += __shfl_xor_sync(0xffffffffu, v, 1, 8);
        v += __shfl_xor_sync(0xffffffffu, v, 2, 8);
        v += __shfl_xor_sync(0xffffffffu, v, 4, 8);
        if (h == sl) ev = v;
    }
    int sid = src[e];
    float x = g_ssrc[(size_t)sid * NH + sl] + ev;
    g_eval[(size_t)e * NH + sl] = (x > 0.f) ? x : 0.01f * x;
}

// ---------------- counting sort of edges by dst ----------------------------
__global__ void k_hist(const int* __restrict__ dst) {
    int t = blockIdx.x * blockDim.x + threadIdx.x;
    if (t < NE) atomicAdd(&g_counts[dst[t]], 1);
}

__global__ void __launch_bounds__(1024) k_scan() {
    __shared__ int sh[1024];
    int t = threadIdx.x;
    int base = t * 10;
    int local[10];
    int s = 0;
#pragma unroll
    for (int i = 0; i < 10; ++i) {
        int idx = base + i;
        int c = (idx < NP) ? g_counts[idx] : 0;
        local[i] = s;
        s += c;
    }
    sh[t] = s;
    __syncthreads();
    for (int off = 1; off < 1024; off <<= 1) {
        int v = (t >= off) ? sh[t - off] : 0;
        __syncthreads();
        sh[t] += v;
        __syncthreads();
    }
    int excl = sh[t] - s;
#pragma unroll
    for (int i = 0; i < 10; ++i) {
        int idx = base + i;
        if (idx < NP) {
            int o = excl + local[i];
            g_offsets[idx] = o;
            g_cursor[idx] = o;
        }
    }
}

__global__ void k_scatter(const int* __restrict__ dst) {
    int t = blockIdx.x * blockDim.x + threadIdx.x;
    if (t < NE) {
        int p = atomicAdd(&g_cursor[dst[t]], 1);
        g_edge_sorted[p] = t;
    }
}

// ---------------- per-segment softmax + weighted gather of z ---------------
__global__ void __launch_bounds__(256) k_segment(const int* __restrict__ src,
                                                 float* __restrict__ out) {
    int p = blockIdx.x;
    int t = threadIdx.x;
    int h = t >> 5;
    int start = g_offsets[p];
    int cnt = g_counts[p];
    float* op = out + (size_t)p * HD + t;
    if (cnt == 0) { *op = 0.f; return; }

    float m = -3.0e38f;
    for (int i = 0; i < cnt; ++i) {
        int eid = g_edge_sorted[start + i];
        m = fmaxf(m, g_eval[(size_t)eid * NH + h]);
    }
    float denom = 0.f, acc = 0.f;
    for (int i = 0; i < cnt; ++i) {
        int eid = g_edge_sorted[start + i];
        float w = expf(g_eval[(size_t)eid * NH + h] - m);
        denom += w;
        int sid = src[eid];
        acc += w * g_z[(size_t)sid * HD + t];
    }
    *op = acc / denom;
}

// ---------------- launcher --------------------------------------------------
extern "C" void kernel_launch(void* const* d_in, const int* in_sizes, int n_in,
                              void* d_out, int out_size) {
    const float* h      = (const float*)d_in[0];
    const float* srl    = (const float*)d_in[1];
    const int*   src    = (const int*)d_in[2];
    const int*   dst    = (const int*)d_in[3];
    const float* W_fc   = (const float*)d_in[4];
    const float* W_feat = (const float*)d_in[5];
    const float* W_attn = (const float*)d_in[6];
    float* out = (float*)d_out;

    static bool attr_set = false;
    if (!attr_set) {
        cudaFuncSetAttribute(k_gemm_bf16pre,
                             cudaFuncAttributeMaxDynamicSharedMemorySize,
                             GEMM_SMEM_BYTES);
        attr_set = true;
    }

    k_zero_counts<<<(NP + 255) / 256, 256>>>();
    k_vfeat<<<(NH * FEAT + 255) / 256, 256>>>(W_feat, W_attn);

    __nv_bfloat16 *ahi, *alo, *bhi, *blo;
    float* zptr;
    cudaGetSymbolAddress((void**)&ahi, g_ahi);
    cudaGetSymbolAddress((void**)&alo, g_alo);
    cudaGetSymbolAddress((void**)&bhi, g_bhi);
    cudaGetSymbolAddress((void**)&blo, g_blo);
    cudaGetSymbolAddress((void**)&zptr, g_z);

    {
        int n4a = NA * IN_DIM / 4;
        k_split<<<(n4a + 255) / 256, 256>>>(h, ahi, alo, n4a);
        int n4b = HD * IN_DIM / 4;
        k_split<<<(n4b + 255) / 256, 256>>>(W_fc, bhi, blo, n4b);
    }

    {
        dim3 grid(HD / GBN, (NA + GBM - 1) / GBM);
        k_gemm_bf16pre<<<grid, 256, GEMM_SMEM_BYTES>>>(ahi, alo, bhi, blo, zptr);
    }

    k_ssrc<<<(NA * 32 + 255) / 256, 256>>>(W_attn);
    k_eval<<<(NE + 31) / 32, 256>>>(srl, src);

    k_hist<<<(NE + 255) / 256, 256>>>(dst);
    k_scan<<<1, 1024>>>();
    k_scatter<<<(NE + 255) / 256, 256>>>(dst);

    k_segment<<<NP, 256>>>(src, out);
}